// round 5
// baseline (speedup 1.0000x reference)
#include <cuda_runtime.h>
#include <math.h>

#define N_ 2048
#define E_ 65536
#define D_ 512

#define MB_ 128                 // persistent blocks (<=148 SMs, all co-resident)
#define MT_ 512                 // threads/block
#define NT_ (MB_ * MT_)         // 65536 threads == E_

// ---------------- static device scratch (no allocations allowed) ----------------
__device__ int   g_degin[N_], g_degout[N_];
__device__ int   g_rpin[N_ + 1], g_rpout[N_ + 1];
__device__ int   g_curin[N_], g_curout[N_];
__device__ int   g_cscsrc[E_];        // CSC: senders grouped by receiver
__device__ int   g_csrdst[E_];        // CSR: dst grouped by src
__device__ float g_csrw[E_];          // prescaled 0.5*w/s_row
__device__ float g_s[N_], g_invs[N_], g_dd[N_], g_diag[N_];
__device__ int   g_bb[N_], g_mis[N_], g_mka[N_], g_mkb[N_], g_a[N_];
__device__ int   g_qlist[N_], g_colmap[N_];
__device__ int   g_M;
__device__ int   g_cluster[N_];
__device__ int   g_counts[N_];
__device__ int   g_cnt[2];
__device__ unsigned g_barcnt;
__device__ unsigned g_barrel;
__device__ float g_B[(size_t)N_ * N_]; // compact rw[:, MIS] (stride = M)

__device__ __forceinline__ int ldvi(const int* p) { return *(const volatile int*)p; }

// ---------------- per-replay reset of barrier words (1 thread) ----------------
__global__ void k_init()
{
    g_cnt[0] = 0; g_cnt[1] = 0; g_barcnt = 0u; g_barrel = 0u;
}

// ---------------- grid barrier: ticket counter + read-only release word ----------------
__device__ __forceinline__ void gridbar(unsigned& ph)
{
    __syncthreads();
    if (threadIdx.x == 0) {
        __threadfence();
        unsigned t = atomicAdd(&g_barcnt, 1u);
        unsigned target = ph * (unsigned)MB_ + (unsigned)MB_;
        if (t + 1u == target) {
            *((volatile unsigned*)&g_barrel) = ph + 1u;     // last arrival releases
        } else {
            while (*((volatile unsigned*)&g_barrel) < ph + 1u) {}
        }
        __threadfence();
    }
    ph++;
    __syncthreads();
}

// ================= THE fused persistent kernel =================
__global__ void __launch_bounds__(MT_, 1)
k_all(const int* __restrict__ ei, const float* __restrict__ ea,
      const float* __restrict__ x, const int* __restrict__ rank,
      const float* __restrict__ u, float* __restrict__ out, int out_size)
{
    const int bid  = blockIdx.x;
    const int t    = threadIdx.x;
    const int tid  = bid * MT_ + t;
    const int lane = tid & 31;

    __shared__ int sA[N_], sB[N_];

    size_t nn = (size_t)N_ * N_;
    float* adjc  = out;
    float* chard = out + nn;
    float* pinv  = out + 2 * nn;
    float* miso  = out + 3 * nn;
    float* xpool = out + 3 * nn + N_;

    unsigned ph = 0;

    // edge tuple cached once, reused in 4 phases (tid == edge id)
    const int   er = ei[tid];
    const int   ec = ei[E_ + tid];
    const float ew = ea[tid];

    // ---- phase 0: zero accumulators (folded from old k_init) ----
    if (tid < N_) { g_degin[tid] = 0; g_degout[tid] = 0; g_s[tid] = 0.f; g_diag[tid] = 0.f; g_counts[tid] = 0; }
    gridbar(ph);

    // ---- phase 1: edge pass 1 (degrees, row sums, diag) ----
    atomicAdd(&g_degin[ec], 1);
    atomicAdd(&g_degout[er], 1);
    atomicAdd(&g_s[er], ew);
    if (er == ec) atomicAdd(&g_diag[er], ew);
    gridbar(ph);

    // ---- phase 2: block0 scans rowptrs; other blocks zero output + invs/dd ----
    if (bid == 0) {
        for (int pass = 0; pass < 2; pass++) {
            const int* src = pass ? g_degout : g_degin;
            int* rp  = pass ? g_rpout : g_rpin;
            int* cur = pass ? g_curout : g_curin;
            for (int i = t; i < N_; i += MT_) sA[i] = src[i];
            __syncthreads();
            int* in = sA; int* outp = sB;
            for (int off = 1; off < N_; off <<= 1) {
                for (int i = t; i < N_; i += MT_)
                    outp[i] = in[i] + (i >= off ? in[i - off] : 0);
                __syncthreads();
                int* tmp = in; in = outp; outp = tmp;
            }
            for (int i = t; i < N_; i += MT_) { rp[i + 1] = in[i]; cur[i] = i ? in[i - 1] : 0; }
            if (t == 0) rp[0] = 0;
            __syncthreads();
        }
    } else {
        int i = (bid - 1) * MT_ + t;
        if (i < N_) {
            float s = g_s[i];
            float inv = s > 0.f ? 1.f / s : 1.f;
            g_invs[i] = inv;
            g_dd[i] = 0.5f * (1.f + g_diag[i] * inv);
        }
        // zero-fill the 54MB output (overlapped with block0's scan)
        float4* o4 = (float4*)out;
        size_t tot4 = (size_t)out_size >> 2;
        for (size_t idx = (size_t)(bid - 1) * MT_ + t; idx < tot4; idx += (size_t)(MB_ - 1) * MT_)
            o4[idx] = make_float4(0.f, 0.f, 0.f, 0.f);
    }
    gridbar(ph);

    // ---- phase 3: edge pass 2 (fill CSC/CSR, prescaled weights) ----
    {
        int p = atomicAdd(&g_curin[ec], 1);
        g_cscsrc[p] = er;
        int q = atomicAdd(&g_curout[er], 1);
        g_csrdst[q] = ec;
        g_csrw[q] = 0.5f * ew * g_invs[er];
    }
    gridbar(ph);

    // ---- phase 4: k-hop MIS. 1 warp per node, reg-cached in-list ----
    const int n = tid >> 5;   // node == warp id (2048 warps)
    for (int i = tid; i < N_; i += NT_) { g_a[i] = rank[i]; g_mis[i] = 0; }
    const int beg = g_rpin[n];
    const int end = g_rpin[n + 1];
    const int deg = end - beg;
    const int src = (lane < deg) ? g_cscsrc[beg + lane] : -1;
    const int rk  = rank[n];
    gridbar(ph);

    for (int iter = 0; iter < N_; iter++) {
        // min-prop hop 1
        {
            int m = ldvi(&g_a[n]);
            if (src >= 0) m = min(m, ldvi(&g_a[src]));
            for (int e = beg + 32 + lane; e < end; e += 32) m = min(m, ldvi(&g_a[g_cscsrc[e]]));
            m = __reduce_min_sync(0xffffffffu, m);
            if (lane == 0) g_bb[n] = m;
        }
        gridbar(ph);
        // min-prop hop 2 + mis update
        {
            int m = ldvi(&g_bb[n]);
            if (src >= 0) m = min(m, ldvi(&g_bb[src]));
            for (int e = beg + 32 + lane; e < end; e += 32) m = min(m, ldvi(&g_bb[g_cscsrc[e]]));
            m = __reduce_min_sync(0xffffffffu, m);
            if (lane == 0) {
                int mi = g_mis[n] | (rk == m ? 1 : 0);
                g_mis[n] = mi;
                g_mka[n] = mi;
            }
        }
        gridbar(ph);
        // or-prop hop 1
        {
            int m = ldvi(&g_mka[n]);
            if (src >= 0) m = max(m, ldvi(&g_mka[src]));
            for (int e = beg + 32 + lane; e < end; e += 32) m = max(m, ldvi(&g_mka[g_cscsrc[e]]));
            m = __reduce_max_sync(0xffffffffu, m);
            if (lane == 0) g_mkb[n] = m;
        }
        gridbar(ph);
        // or-prop hop 2 + finalize; straggler count via __syncthreads_count
        if (tid == 0) g_cnt[(iter + 1) & 1] = 0;
        int notmask;
        {
            int m = ldvi(&g_mkb[n]);
            if (src >= 0) m = max(m, ldvi(&g_mkb[src]));
            for (int e = beg + 32 + lane; e < end; e += 32) m = max(m, ldvi(&g_mkb[g_cscsrc[e]]));
            m = __reduce_max_sync(0xffffffffu, m);
            int mask = m > 0;
            if (lane == 0) g_a[n] = mask ? N_ : rk;
            notmask = (lane == 0 && !mask) ? 1 : 0;
        }
        int blkcnt = __syncthreads_count(notmask);
        if (t == 0 && blkcnt) atomicAdd(&g_cnt[iter & 1], blkcnt);
        gridbar(ph);
        // exit check: ONE global load per block, broadcast via smem
        if (t == 0) sA[0] = ldvi(&g_cnt[iter & 1]);
        __syncthreads();
        int done = (sA[0] == 0);
        __syncthreads();          // protect sA[0] before any reuse
        if (done) break;
    }

    // ---- compact (block 0) -> colmap/qlist/M ----
    if (bid == 0) {
        for (int i = t; i < N_; i += MT_) sA[i] = ldvi(&g_mis[i]);
        __syncthreads();
        int* in = sA; int* outp = sB;
        for (int off = 1; off < N_; off <<= 1) {
            for (int i = t; i < N_; i += MT_)
                outp[i] = in[i] + (i >= off ? in[i - off] : 0);
            __syncthreads();
            int* tmp = in; in = outp; outp = tmp;
        }
        for (int i = t; i < N_; i += MT_) {
            if (ldvi(&g_mis[i])) { int p = in[i] - 1; g_colmap[i] = p; g_qlist[p] = i; }
            else g_colmap[i] = -1;
        }
        if (t == 0) g_M = in[N_ - 1];
    }
    gridbar(ph);

    // M: one load per block, broadcast via smem
    if (t == 0) sA[0] = ldvi(&g_M);
    __syncthreads();
    const int M = sA[0];
    __syncthreads();

    // ---- zero B ----
    {
        size_t tot = (size_t)N_ * (size_t)M;
        for (size_t idx = tid; idx < tot; idx += NT_) g_B[idx] = 0.f;
    }
    gridbar(ph);

    // ---- build B = rw[:, MIS] ----
    {
        int cm = g_colmap[ec];
        if (cm >= 0) atomicAdd(&g_B[(size_t)er * M + cm], 0.5f * ew * g_invs[er]);
        if (tid < N_ && g_mis[tid])
            atomicAdd(&g_B[(size_t)tid * M + g_colmap[tid]], g_dd[tid]);
    }
    gridbar(ph);

    // ---- SpMM c = rw @ B (warp per row) + fused Gumbel argmax + counts ----
    {
        int i = n;   // row == warp id
        int rb = g_rpout[i], re = g_rpout[i + 1];
        float dd = g_dd[i];
        const float* ui = u + (size_t)i * N_;
        float best = -INFINITY; int bq = 0x7FFFFFFF;
        for (int m0 = 0; m0 < M; m0 += 32) {
            int m = m0 + lane;
            if (m < M) {
                float acc = dd * g_B[(size_t)i * M + m];
                for (int e = rb; e < re; e++)
                    acc += g_csrw[e] * g_B[(size_t)g_csrdst[e] * M + m];
                if (acc > 0.f) {
                    int q = g_qlist[m];
                    float uu = ui[q];
                    float gum = -logf(-logf(uu + 1e-20f) + 1e-20f);
                    float lg = logf(fmaxf(acc, 1e-30f)) + gum;
                    if (lg > best || (lg == best && q < bq)) { best = lg; bq = q; }
                }
            }
        }
        for (int o = 16; o > 0; o >>= 1) {
            float v = __shfl_xor_sync(0xffffffffu, best, o);
            int   q = __shfl_xor_sync(0xffffffffu, bq, o);
            if (v > best || (v == best && q < bq)) { best = v; bq = q; }
        }
        if (lane == 0) {
            int cl = (bq == 0x7FFFFFFF) ? 0 : bq;
            g_cluster[i] = cl;
            atomicAdd(&g_counts[cl], 1);
        }
    }
    gridbar(ph);

    // ---- post: miso/chard/pinv + adj_c + x_pool ----
    if (tid < N_) {
        int i = tid;
        miso[i] = g_mis[i] ? 1.f : 0.f;
        int c = g_cluster[i];
        chard[(size_t)i * N_ + c] = 1.f;
        pinv[(size_t)c * N_ + i] = 1.f / (float)g_counts[c];
    }
    atomicAdd(&adjc[(size_t)g_cluster[er] * N_ + g_cluster[ec]], ew);
    for (int idx = tid; idx < N_ * D_; idx += NT_) {
        int i = idx >> 9, d = idx & (D_ - 1);      // D_ = 512
        int c = g_cluster[i];
        float invc = 1.f / (float)g_counts[c];
        atomicAdd(&xpool[(size_t)c * D_ + d], x[idx] * invc);
    }
}

// ---------------- launch ----------------
extern "C" void kernel_launch(void* const* d_in, const int* in_sizes, int n_in,
                              void* d_out, int out_size)
{
    const int*   ei   = (const int*)d_in[0];     // edge_index [2, E]
    const float* ea   = (const float*)d_in[1];   // edge_attr  [E]
    const float* x    = (const float*)d_in[2];   // x          [N, D]
    const int*   rank = (const int*)d_in[3];     // rank       [N]
    const float* u    = (const float*)d_in[4];   // u          [N, N]

    (void)in_sizes; (void)n_in;

    k_init<<<1, 1>>>();
    k_all <<<MB_, MT_>>>(ei, ea, x, rank, u, (float*)d_out, out_size);
}

// round 6
// speedup vs baseline: 1.0158x; 1.0158x over previous
#include <cuda_runtime.h>
#include <math.h>

#define N_ 2048
#define E_ 65536
#define D_ 512

#define MB_ 128                 // persistent blocks (all co-resident on 148 SMs)
#define MT_ 512                 // threads/block
#define NT_ (MB_ * MT_)         // 65536 threads == E_

// ---------------- static device scratch (no allocations allowed) ----------------
__device__ int   g_degin[N_], g_degout[N_];
__device__ int   g_rpin[N_ + 1], g_rpout[N_ + 1];
__device__ int   g_curin[N_], g_curout[N_];
__device__ int   g_cscsrc[E_];        // CSC: senders grouped by receiver
__device__ int   g_csrdst[E_];        // CSR: dst grouped by src
__device__ float g_csrw[E_];          // prescaled 0.5*w/s_row
__device__ float g_s[N_], g_invs[N_], g_dd[N_], g_diag[N_];
__device__ int   g_bb[N_], g_mis[N_], g_mka[N_], g_mkb[N_], g_a[N_];
__device__ int   g_qlist[N_], g_colmap[N_];
__device__ int   g_M;
__device__ int   g_cluster[N_];       // cluster id (original node index q)
__device__ int   g_clustc[N_];        // compact cluster index (0..M-1, M = fallback)
__device__ int   g_counts[N_];
__device__ unsigned g_strag[2];
__device__ unsigned g_barcnt;
__device__ unsigned g_barrel;         // release word: 2*phase (+1 = "stragglers remain")
__device__ float g_B[(size_t)N_ * N_]; // compact rw[:, MIS] (stride = M)

__device__ __forceinline__ int ldvi(const int* p) { return *(const volatile int*)p; }

// ---------------- per-replay init: zero accumulators + barrier words ----------------
__global__ void k_init()
{
    int i = blockIdx.x * blockDim.x + threadIdx.x;
    if (i < N_) { g_degin[i] = 0; g_degout[i] = 0; g_s[i] = 0.f; g_diag[i] = 0.f; g_counts[i] = 0; }
    if (i == 0) { g_strag[0] = 0u; g_strag[1] = 0u; g_barcnt = 0u; g_barrel = 0u; }
}

// ---------------- grid barrier: ticket counter + monotonic release word ----------------
__device__ __forceinline__ void gridbar(unsigned& ph)
{
    __syncthreads();
    if (threadIdx.x == 0) {
        __threadfence();
        unsigned a = atomicAdd(&g_barcnt, 1u);
        unsigned rel = 2u * (ph + 1u);
        if (a + 1u == (ph + 1u) * (unsigned)MB_) {
            *((volatile unsigned*)&g_barrel) = rel;     // last arrival releases
        } else {
            while (*((volatile unsigned*)&g_barrel) < rel) {}
        }
        __threadfence();
    }
    ph++;
    __syncthreads();
}

// ================= THE fused persistent kernel =================
__global__ void __launch_bounds__(MT_, 1)
k_all(const int* __restrict__ ei, const float* __restrict__ ea,
      const float* __restrict__ x, const int* __restrict__ rank,
      const float* __restrict__ u, float* __restrict__ out, int out_size)
{
    const int bid  = blockIdx.x;
    const int t    = threadIdx.x;
    const int tid  = bid * MT_ + t;
    const int lane = tid & 31;

    __shared__ int sMem[2 * N_];          // scan buffers / adjc aggregation tile
    __shared__ int sFlag;
    int* sA = sMem;
    int* sB = sMem + N_;

    size_t nn = (size_t)N_ * N_;
    float* adjc  = out;
    float* chard = out + nn;
    float* pinv  = out + 2 * nn;
    float* miso  = out + 3 * nn;
    float* xpool = out + 3 * nn + N_;

    unsigned ph = 0;

    // edge tuple cached once, reused across phases (tid == edge id)
    const int   er = ei[tid];
    const int   ec = ei[E_ + tid];
    const float ew = ea[tid];

    // ---- phase 1: edge pass 1 (degrees, row sums, diag) ----
    atomicAdd(&g_degin[ec], 1);
    atomicAdd(&g_degout[er], 1);
    atomicAdd(&g_s[er], ew);
    if (er == ec) atomicAdd(&g_diag[er], ew);
    gridbar(ph);

    // ---- phase 2: block0 scans rowptrs; other blocks zero output + invs/dd ----
    if (bid == 0) {
        for (int pass = 0; pass < 2; pass++) {
            const int* src = pass ? g_degout : g_degin;
            int* rp  = pass ? g_rpout : g_rpin;
            int* cur = pass ? g_curout : g_curin;
            for (int i = t; i < N_; i += MT_) sA[i] = src[i];
            __syncthreads();
            int* in = sA; int* outp = sB;
            for (int off = 1; off < N_; off <<= 1) {
                for (int i = t; i < N_; i += MT_)
                    outp[i] = in[i] + (i >= off ? in[i - off] : 0);
                __syncthreads();
                int* tmp = in; in = outp; outp = tmp;
            }
            for (int i = t; i < N_; i += MT_) { rp[i + 1] = in[i]; cur[i] = i ? in[i - 1] : 0; }
            if (t == 0) rp[0] = 0;
            __syncthreads();
        }
    } else {
        int i = (bid - 1) * MT_ + t;
        if (i < N_) {
            float s = g_s[i];
            float inv = s > 0.f ? 1.f / s : 1.f;
            g_invs[i] = inv;
            g_dd[i] = 0.5f * (1.f + g_diag[i] * inv);
        }
        // zero-fill the 54MB output (overlapped with block0's scan)
        float4* o4 = (float4*)out;
        size_t tot4 = (size_t)out_size >> 2;
        for (size_t idx = (size_t)(bid - 1) * MT_ + t; idx < tot4; idx += (size_t)(MB_ - 1) * MT_)
            o4[idx] = make_float4(0.f, 0.f, 0.f, 0.f);
    }
    gridbar(ph);

    // ---- phase 3: edge pass 2 (fill CSC/CSR, prescaled weights) ----
    {
        int p = atomicAdd(&g_curin[ec], 1);
        g_cscsrc[p] = er;
        int q = atomicAdd(&g_curout[er], 1);
        g_csrdst[q] = ec;
        g_csrw[q] = 0.5f * ew * g_invs[er];
    }
    gridbar(ph);

    // ---- phase 4: k-hop MIS. 1 warp/node, reg-cached in-list, reg-carried state ----
    const int n = tid >> 5;   // node == warp id (2048 warps)
    {
        for (int i = tid; i < N_; i += NT_) g_a[i] = rank[i];
    }
    const int beg = g_rpin[n];
    const int end = g_rpin[n + 1];
    const int deg = end - beg;
    const int src = (lane < deg) ? g_cscsrc[beg + lane] : -1;
    const int rk  = rank[n];
    int misreg = 0;
    int areg   = rk;
    gridbar(ph);

    for (int iter = 0; iter < N_; iter++) {
        // min-prop hop 1 (self value carried in register)
        int m1 = areg;
        if (src >= 0) m1 = min(m1, ldvi(&g_a[src]));
        for (int e = beg + 32 + lane; e < end; e += 32) m1 = min(m1, ldvi(&g_a[g_cscsrc[e]]));
        m1 = __reduce_min_sync(0xffffffffu, m1);
        if (lane == 0) g_bb[n] = m1;
        gridbar(ph);

        // min-prop hop 2 + mis update (hop-1 result already in register)
        int m2 = m1;
        if (src >= 0) m2 = min(m2, ldvi(&g_bb[src]));
        for (int e = beg + 32 + lane; e < end; e += 32) m2 = min(m2, ldvi(&g_bb[g_cscsrc[e]]));
        m2 = __reduce_min_sync(0xffffffffu, m2);
        misreg |= (rk == m2) ? 1 : 0;
        if (lane == 0) g_mka[n] = misreg;
        gridbar(ph);

        // or-prop hop 1
        int o1 = misreg;
        if (src >= 0) o1 = max(o1, ldvi(&g_mka[src]));
        for (int e = beg + 32 + lane; e < end; e += 32) o1 = max(o1, ldvi(&g_mka[g_cscsrc[e]]));
        o1 = __reduce_max_sync(0xffffffffu, o1);
        if (lane == 0) g_mkb[n] = o1;
        gridbar(ph);

        // or-prop hop 2 + finalize
        int o2 = o1;
        if (src >= 0) o2 = max(o2, ldvi(&g_mkb[src]));
        for (int e = beg + 32 + lane; e < end; e += 32) o2 = max(o2, ldvi(&g_mkb[g_cscsrc[e]]));
        o2 = __reduce_max_sync(0xffffffffu, o2);
        int mask = o2 > 0;
        areg = mask ? N_ : rk;
        if (lane == 0) g_a[n] = areg;
        int notmask = (lane == 0 && !mask) ? 1 : 0;
        int blkcnt = __syncthreads_count(notmask);

        // finalize barrier with embedded straggler flag (no extra poll round-trip)
        int parity = iter & 1;
        if (t == 0) {
            if (blkcnt) atomicAdd(&g_strag[parity], (unsigned)blkcnt);
            __threadfence();
            unsigned a = atomicAdd(&g_barcnt, 1u);
            unsigned rel = 2u * (ph + 1u);
            unsigned flag;
            if (a + 1u == (ph + 1u) * (unsigned)MB_) {
                unsigned s = *((volatile unsigned*)&g_strag[parity]);
                g_strag[parity ^ 1] = 0u;      // reset other parity for next iter
                flag = s ? 1u : 0u;
                __threadfence();
                *((volatile unsigned*)&g_barrel) = rel + flag;
            } else {
                unsigned v;
                while ((v = *((volatile unsigned*)&g_barrel)) < rel) {}
                flag = v & 1u;
            }
            __threadfence();
            sFlag = (int)flag;
        }
        ph++;
        __syncthreads();
        if (sFlag == 0) break;
    }
    if (lane == 0) g_mis[n] = misreg;
    gridbar(ph);      // publish g_mis before compact

    // ---- compact (block 0) -> colmap/qlist/M ----
    if (bid == 0) {
        for (int i = t; i < N_; i += MT_) sA[i] = ldvi(&g_mis[i]);
        __syncthreads();
        int* in = sA; int* outp = sB;
        for (int off = 1; off < N_; off <<= 1) {
            for (int i = t; i < N_; i += MT_)
                outp[i] = in[i] + (i >= off ? in[i - off] : 0);
            __syncthreads();
            int* tmp = in; in = outp; outp = tmp;
        }
        for (int i = t; i < N_; i += MT_) {
            if (ldvi(&g_mis[i])) { int p = in[i] - 1; g_colmap[i] = p; g_qlist[p] = i; }
            else g_colmap[i] = -1;
        }
        if (t == 0) g_M = in[N_ - 1];
    }
    gridbar(ph);

    // M: one load per block, broadcast via smem
    if (t == 0) sFlag = ldvi(&g_M);
    __syncthreads();
    const int M = sFlag;
    __syncthreads();

    // ---- zero B ----
    {
        size_t tot = (size_t)N_ * (size_t)M;
        for (size_t idx = tid; idx < tot; idx += NT_) g_B[idx] = 0.f;
    }
    gridbar(ph);

    // ---- build B = rw[:, MIS] ----
    {
        int cm = g_colmap[ec];
        if (cm >= 0) atomicAdd(&g_B[(size_t)er * M + cm], 0.5f * ew * g_invs[er]);
        if (tid < N_ && g_mis[tid])
            atomicAdd(&g_B[(size_t)tid * M + g_colmap[tid]], g_dd[tid]);
    }
    gridbar(ph);

    // ---- SpMM c = rw @ B (warp per row) + fused Gumbel argmax + counts ----
    {
        int i = n;   // row == warp id
        int rb = g_rpout[i], re = g_rpout[i + 1];
        float dd = g_dd[i];
        const float* ui = u + (size_t)i * N_;
        float best = -INFINITY; int bq = 0x7FFFFFFF; int bm = 0;
        for (int m0 = 0; m0 < M; m0 += 32) {
            int m = m0 + lane;
            if (m < M) {
                float acc = dd * g_B[(size_t)i * M + m];
                for (int e = rb; e < re; e++)
                    acc += g_csrw[e] * g_B[(size_t)g_csrdst[e] * M + m];
                if (acc > 0.f) {
                    int q = g_qlist[m];
                    float uu = ui[q];
                    float gum = -logf(-logf(uu + 1e-20f) + 1e-20f);
                    float lg = logf(fmaxf(acc, 1e-30f)) + gum;
                    if (lg > best || (lg == best && q < bq)) { best = lg; bq = q; bm = m; }
                }
            }
        }
        for (int o = 16; o > 0; o >>= 1) {
            float v  = __shfl_xor_sync(0xffffffffu, best, o);
            int   q  = __shfl_xor_sync(0xffffffffu, bq, o);
            int   mm = __shfl_xor_sync(0xffffffffu, bm, o);
            if (v > best || (v == best && q < bq)) { best = v; bq = q; bm = mm; }
        }
        if (lane == 0) {
            int cm, cl;
            if (bq == 0x7FFFFFFF) { cm = M; cl = 0; }   // all-(-inf): argmax = 0
            else { cm = bm; cl = bq; }
            g_clustc[i]  = cm;
            g_cluster[i] = cl;
            atomicAdd(&g_counts[cl], 1);
        }
    }
    gridbar(ph);

    // ---- post: miso/chard/pinv + adj_c (smem-aggregated) + x_pool ----
    if (tid < N_) {
        int i = tid;
        miso[i] = g_mis[i] ? 1.f : 0.f;
        int c = g_cluster[i];
        chard[(size_t)i * N_ + c] = 1.f;
        pinv[(size_t)c * N_ + i] = 1.f / (float)g_counts[c];
    }

    // adj_c: block-level smem aggregation kills same-address L2 atomic serialization
    {
        const int Mp1 = M + 1;                     // slot M = fallback cluster (node 0)
        if (Mp1 * Mp1 <= 2 * N_) {
            float* sbuf = (float*)sMem;
            for (int i2 = t; i2 < Mp1 * Mp1; i2 += MT_) sbuf[i2] = 0.f;
            __syncthreads();
            atomicAdd(&sbuf[g_clustc[er] * Mp1 + g_clustc[ec]], ew);
            __syncthreads();
            for (int i2 = t; i2 < Mp1 * Mp1; i2 += MT_) {
                float v = sbuf[i2];
                if (v != 0.f) {
                    int m1 = i2 / Mp1, m2 = i2 % Mp1;
                    int r = (m1 < M) ? g_qlist[m1] : 0;
                    int c = (m2 < M) ? g_qlist[m2] : 0;
                    atomicAdd(&adjc[(size_t)r * N_ + c], v);
                }
            }
        } else {
            atomicAdd(&adjc[(size_t)g_cluster[er] * N_ + g_cluster[ec]], ew);
        }
    }

    for (int idx = tid; idx < N_ * D_; idx += NT_) {
        int i = idx >> 9, d = idx & (D_ - 1);      // D_ = 512
        int c = g_cluster[i];
        float invc = 1.f / (float)g_counts[c];
        atomicAdd(&xpool[(size_t)c * D_ + d], x[idx] * invc);
    }
}

// ---------------- launch ----------------
extern "C" void kernel_launch(void* const* d_in, const int* in_sizes, int n_in,
                              void* d_out, int out_size)
{
    const int*   ei   = (const int*)d_in[0];     // edge_index [2, E]
    const float* ea   = (const float*)d_in[1];   // edge_attr  [E]
    const float* x    = (const float*)d_in[2];   // x          [N, D]
    const int*   rank = (const int*)d_in[3];     // rank       [N]
    const float* u    = (const float*)d_in[4];   // u          [N, N]

    (void)in_sizes; (void)n_in;

    k_init<<<8, 256>>>();
    k_all <<<MB_, MT_>>>(ei, ea, x, rank, u, (float*)d_out, out_size);
}